// round 6
// baseline (speedup 1.0000x reference)
#include <cuda_runtime.h>
#include <cuda_fp16.h>
#include <cstdint>
#include <cstddef>

// W8A16 GEMM, legacy-HMMA path (harness compiles for plain sm_103: no tcgen05).
// Contract (confirmed R4): X f32[M,K] (fp16-valued), W int32[N,K] (int8-valued),
// scale/bias f32[N], out f32[M,N] (fp16-rounded values).
// Pass 1: X->fp16 scratch, W->fp16 scratch (device globals).
// Pass 2: GEMM 128x256 CTA tile, BK=64, 8 warps with 64x64 warp tiles,
// 3-stage cp.async pipeline (wait_group 1), SW128 smem, ldmatrix + mma.sync.

namespace {

constexpr int MM = 8192, KK = 4096, NN = 11008;
constexpr int BM = 128, BN = 256, BK = 64;
constexpr int THREADS = 256;
constexpr int STAGES = 3;
constexpr int ASTAGE = BM * 128;   // 16 KB
constexpr int BSTAGE = BN * 128;   // 32 KB
constexpr int SMEM_TOTAL = STAGES * (ASTAGE + BSTAGE);  // 147456 B

__device__ __align__(256) __half g_X16[(size_t)MM * KK];   // 64 MB
__device__ __align__(256) __half g_W16[(size_t)NN * KK];   // 90 MB

// ---------------- converters ----------------
__global__ void __launch_bounds__(256) cvt_x(const float* __restrict__ x, int total8) {
    int t = blockIdx.x * blockDim.x + threadIdx.x;
    if (t >= total8) return;
    size_t base = (size_t)t * 8;
    const float4* p = (const float4*)(x + base);
    float4 a = p[0], b = p[1];
    __half2 h0 = __floats2half2_rn(a.x, a.y), h1 = __floats2half2_rn(a.z, a.w);
    __half2 h2 = __floats2half2_rn(b.x, b.y), h3 = __floats2half2_rn(b.z, b.w);
    uint4 o;
    o.x = *(uint32_t*)&h0; o.y = *(uint32_t*)&h1;
    o.z = *(uint32_t*)&h2; o.w = *(uint32_t*)&h3;
    *(uint4*)(g_X16 + base) = o;
}

__global__ void __launch_bounds__(256) cvt_w(const int* __restrict__ w, int total8) {
    int t = blockIdx.x * blockDim.x + threadIdx.x;
    if (t >= total8) return;
    size_t base = (size_t)t * 8;
    const int4* p = (const int4*)(w + base);
    int4 a = p[0], b = p[1];
    __half h[8];
    h[0] = __int2half_rn(a.x); h[1] = __int2half_rn(a.y);
    h[2] = __int2half_rn(a.z); h[3] = __int2half_rn(a.w);
    h[4] = __int2half_rn(b.x); h[5] = __int2half_rn(b.y);
    h[6] = __int2half_rn(b.z); h[7] = __int2half_rn(b.w);
    uint4 o;
    o.x = *(uint32_t*)&h[0]; o.y = *(uint32_t*)&h[2];
    o.z = *(uint32_t*)&h[4]; o.w = *(uint32_t*)&h[6];
    *(uint4*)(g_W16 + base) = o;
}

// ---------------- helpers ----------------
__device__ __forceinline__ uint32_t swz(uint32_t x) { return x ^ ((x >> 3) & 0x70); }

__device__ __forceinline__ void cp_async16(uint32_t dst, const void* src) {
    asm volatile("cp.async.cg.shared.global [%0], [%1], 16;\n" :: "r"(dst), "l"(src));
}
__device__ __forceinline__ void cp_commit() { asm volatile("cp.async.commit_group;\n"); }
template <int N>
__device__ __forceinline__ void cp_wait() {
    asm volatile("cp.async.wait_group %0;\n" :: "n"(N) : "memory");
}

__device__ __forceinline__ void ldsm4(uint32_t r[4], uint32_t addr) {
    asm volatile("ldmatrix.sync.aligned.m8n8.x4.shared.b16 {%0,%1,%2,%3}, [%4];\n"
                 : "=r"(r[0]), "=r"(r[1]), "=r"(r[2]), "=r"(r[3]) : "r"(addr));
}

__device__ __forceinline__ void mma16816(float c[4], const uint32_t a[4],
                                         uint32_t b0, uint32_t b1) {
    asm volatile("mma.sync.aligned.m16n8k16.row.col.f32.f16.f16.f32 "
                 "{%0,%1,%2,%3}, {%4,%5,%6,%7}, {%8,%9}, {%0,%1,%2,%3};\n"
                 : "+f"(c[0]), "+f"(c[1]), "+f"(c[2]), "+f"(c[3])
                 : "r"(a[0]), "r"(a[1]), "r"(a[2]), "r"(a[3]), "r"(b0), "r"(b1));
}

__device__ __forceinline__ float rf16(float v) {
    return __half2float(__float2half_rn(v));
}

// ---------------- GEMM ----------------
__global__ void __launch_bounds__(THREADS, 1)
gemm_kernel(const float* __restrict__ scale, const float* __restrict__ bias,
            float* __restrict__ out, int M, int N, int K)
{
    extern __shared__ __align__(1024) char smem[];
    const uint32_t sA = (uint32_t)__cvta_generic_to_shared(smem);
    const uint32_t sB = sA + STAGES * ASTAGE;

    const int tid  = threadIdx.x;
    const int lane = tid & 31;
    const int warp = tid >> 5;
    const int wm = warp >> 2;   // 2 warp rows x 64 M
    const int wn = warp & 3;    // 4 warp cols x 64 N

    const int m0 = blockIdx.x * BM;   // x = M: A slab stays L2-resident across wave
    const int n0 = blockIdx.y * BN;
    const int KT = K / BK;

    // staging: A 1024 chunks (4/thread), B 2048 chunks (8/thread); 16B each
    uint32_t a_st[4]; const __half* a_g[4];
#pragma unroll
    for (int i = 0; i < 4; i++) {
        int chunk = tid + i * THREADS;
        int row = chunk >> 3, c = chunk & 7;
        a_st[i] = swz((uint32_t)(row * 128 + c * 16));
        a_g[i]  = g_X16 + (size_t)(m0 + row) * K + c * 8;
    }
    uint32_t b_st[8]; const __half* b_g[8];
#pragma unroll
    for (int i = 0; i < 8; i++) {
        int chunk = tid + i * THREADS;
        int row = chunk >> 3, c = chunk & 7;
        b_st[i] = swz((uint32_t)(row * 128 + c * 16));
        b_g[i]  = g_W16 + (size_t)(n0 + row) * K + c * 8;
    }

    // ldmatrix base offsets (swizzle xor is row-only -> constant per thread)
    const uint32_t a_off0 = (uint32_t)((wm * 64 + (lane & 15)) * 128 + (lane >> 4) * 16);
    const uint32_t axor   = (a_off0 >> 3) & 0x70;
    const uint32_t b_off0 = (uint32_t)((wn * 64 + ((lane >> 4) & 1) * 8 + (lane & 7)) * 128
                                       + ((lane >> 3) & 1) * 16);
    const uint32_t bxor   = (b_off0 >> 3) & 0x70;

    float acc[4][8][4];
#pragma unroll
    for (int mi = 0; mi < 4; mi++)
#pragma unroll
        for (int ni = 0; ni < 8; ni++)
#pragma unroll
            for (int e = 0; e < 4; e++) acc[mi][ni][e] = 0.f;

    // prologue: stages 0 and 1
#pragma unroll
    for (int s = 0; s < 2; s++) {
        const size_t ko = (size_t)s * BK;
#pragma unroll
        for (int i = 0; i < 4; i++) cp_async16(sA + s * ASTAGE + a_st[i], a_g[i] + ko);
#pragma unroll
        for (int i = 0; i < 8; i++) cp_async16(sB + s * BSTAGE + b_st[i], b_g[i] + ko);
        cp_commit();
    }
    cp_wait<1>();          // stage 0 resident
    __syncthreads();

    for (int kt = 0; kt < KT; ++kt) {
        // issue loads for kt+2 (into the buffer freed at end of kt-1)
        if (kt + 2 < KT) {
            const int s = (kt + 2) % STAGES;
            const size_t ko = (size_t)(kt + 2) * BK;
#pragma unroll
            for (int i = 0; i < 4; i++) cp_async16(sA + s * ASTAGE + a_st[i], a_g[i] + ko);
#pragma unroll
            for (int i = 0; i < 8; i++) cp_async16(sB + s * BSTAGE + b_st[i], b_g[i] + ko);
            cp_commit();
        }

        // compute stage kt
        const uint32_t Abase = sA + (kt % STAGES) * ASTAGE;
        const uint32_t Bbase = sB + (kt % STAGES) * BSTAGE;
#pragma unroll
        for (int ks = 0; ks < 4; ++ks) {
            uint32_t a[4][4];
#pragma unroll
            for (int mi = 0; mi < 4; mi++)
                ldsm4(a[mi], Abase + ((a_off0 + mi * 2048 + ks * 32) ^ axor));
#pragma unroll
            for (int np = 0; np < 4; np++) {
                uint32_t b[4];
                ldsm4(b, Bbase + ((b_off0 + np * 2048 + ks * 32) ^ bxor));
#pragma unroll
                for (int mi = 0; mi < 4; mi++) {
                    mma16816(acc[mi][2 * np],     a[mi], b[0], b[1]);
                    mma16816(acc[mi][2 * np + 1], a[mi], b[2], b[3]);
                }
            }
        }

        // ensure stage kt+1 resident before next iteration
        if (kt + 1 < KT) {
            if (kt + 2 < KT) cp_wait<1>(); else cp_wait<0>();
            __syncthreads();
        }
    }

    // epilogue: scale + bias, round through fp16, f32 out
    const int gi = lane >> 2;
    const int tl = lane & 3;
#pragma unroll
    for (int ni = 0; ni < 8; ni++) {
        const int n = n0 + wn * 64 + ni * 8 + tl * 2;
        const float s0 = __ldg(scale + n), s1 = __ldg(scale + n + 1);
        const float z0 = __ldg(bias + n),  z1 = __ldg(bias + n + 1);
#pragma unroll
        for (int mi = 0; mi < 4; mi++) {
            const size_t r0 = (size_t)(m0 + wm * 64 + mi * 16 + gi);
            *(float2*)(out + r0 * N + n) =
                make_float2(rf16(acc[mi][ni][0] * s0 + z0), rf16(acc[mi][ni][1] * s1 + z1));
            *(float2*)(out + (r0 + 8) * N + n) =
                make_float2(rf16(acc[mi][ni][2] * s0 + z0), rf16(acc[mi][ni][3] * s1 + z1));
        }
    }
}

struct ForceLoad {
    ForceLoad() {
        cudaFuncAttributes a;
        cudaFuncGetAttributes(&a, (const void*)cvt_x);
        cudaFuncGetAttributes(&a, (const void*)cvt_w);
        cudaFuncGetAttributes(&a, (const void*)gemm_kernel);
        cudaFuncSetAttribute((const void*)gemm_kernel,
                             cudaFuncAttributeMaxDynamicSharedMemorySize, SMEM_TOTAL);
    }
};
ForceLoad g_forceload;

} // namespace

extern "C" void kernel_launch(void* const* d_in, const int* in_sizes, int n_in,
                              void* d_out, int out_size) {
    const float* X     = (const float*)d_in[0];
    const int*   W     = (const int*)d_in[1];
    const float* scale = (const float*)d_in[2];
    const float* bias  = (const float*)d_in[3];
    float* out = (float*)d_out;

    const int n0 = in_sizes[0];
    const int n1 = in_sizes[1];
    const int N  = in_sizes[2];            // 11008
    const int K  = n1 / N;                 // 4096
    const int M  = n0 / K;                 // 8192

    cvt_x<<<(n0 / 8 + 255) / 256, 256>>>(X, n0 / 8);
    cvt_w<<<(n1 / 8 + 255) / 256, 256>>>(W, n1 / 8);

    cudaFuncSetAttribute((const void*)gemm_kernel,
                         cudaFuncAttributeMaxDynamicSharedMemorySize, SMEM_TOTAL);
    dim3 grid(M / BM, N / BN);             // 64 x 43
    gemm_kernel<<<grid, THREADS, SMEM_TOTAL>>>(scale, bias, out, M, N, K);
}

// round 7
// speedup vs baseline: 1.1178x; 1.1178x over previous
#include <cuda_runtime.h>
#include <cuda_fp16.h>
#include <cstdint>
#include <cstddef>

// W8A16 GEMM, legacy-HMMA path (harness targets plain sm_103: tcgen05 unavailable).
// Contract (confirmed R4): X f32[M,K] (fp16-valued), W int32[N,K] (int8-valued),
// scale/bias f32[N], out f32[M,N] (fp16-rounded values).
// Pass 1: X->fp16 scratch, W->fp16 scratch (device globals).
// Pass 2: GEMM 128x128 CTA tile, BK=64, 8 warps (32x64 warp tiles),
// 3-stage cp.async ring (wait_group 1), SW128 smem, ldmatrix + mma.sync,
// 2 CTAs/SM so stage-boundary bubbles overlap across CTAs.

namespace {

constexpr int MM = 8192, KK = 4096, NN = 11008;
constexpr int BM = 128, BN = 128, BK = 64;
constexpr int THREADS = 256;
constexpr int STAGES = 3;
constexpr int ASTAGE = BM * 128;   // 16 KB
constexpr int BSTAGE = BN * 128;   // 16 KB
constexpr int SMEM_TOTAL = STAGES * (ASTAGE + BSTAGE);  // 96 KB

__device__ __align__(256) __half g_X16[(size_t)MM * KK];   // 64 MB
__device__ __align__(256) __half g_W16[(size_t)NN * KK];   // 90 MB

// ---------------- converters ----------------
__global__ void __launch_bounds__(256) cvt_x(const float* __restrict__ x, int total8) {
    int t = blockIdx.x * blockDim.x + threadIdx.x;
    if (t >= total8) return;
    size_t base = (size_t)t * 8;
    const float4* p = (const float4*)(x + base);
    float4 a = p[0], b = p[1];
    __half2 h0 = __floats2half2_rn(a.x, a.y), h1 = __floats2half2_rn(a.z, a.w);
    __half2 h2 = __floats2half2_rn(b.x, b.y), h3 = __floats2half2_rn(b.z, b.w);
    uint4 o;
    o.x = *(uint32_t*)&h0; o.y = *(uint32_t*)&h1;
    o.z = *(uint32_t*)&h2; o.w = *(uint32_t*)&h3;
    *(uint4*)(g_X16 + base) = o;
}

__global__ void __launch_bounds__(256) cvt_w(const int* __restrict__ w, int total8) {
    int t = blockIdx.x * blockDim.x + threadIdx.x;
    if (t >= total8) return;
    size_t base = (size_t)t * 8;
    const int4* p = (const int4*)(w + base);
    int4 a = p[0], b = p[1];
    __half h[8];
    h[0] = __int2half_rn(a.x); h[1] = __int2half_rn(a.y);
    h[2] = __int2half_rn(a.z); h[3] = __int2half_rn(a.w);
    h[4] = __int2half_rn(b.x); h[5] = __int2half_rn(b.y);
    h[6] = __int2half_rn(b.z); h[7] = __int2half_rn(b.w);
    uint4 o;
    o.x = *(uint32_t*)&h[0]; o.y = *(uint32_t*)&h[2];
    o.z = *(uint32_t*)&h[4]; o.w = *(uint32_t*)&h[6];
    *(uint4*)(g_W16 + base) = o;
}

// ---------------- helpers ----------------
__device__ __forceinline__ uint32_t swz(uint32_t x) { return x ^ ((x >> 3) & 0x70); }

__device__ __forceinline__ void cp_async16(uint32_t dst, const void* src) {
    asm volatile("cp.async.cg.shared.global [%0], [%1], 16;\n" :: "r"(dst), "l"(src));
}
__device__ __forceinline__ void cp_commit() { asm volatile("cp.async.commit_group;\n"); }
template <int N>
__device__ __forceinline__ void cp_wait() {
    asm volatile("cp.async.wait_group %0;\n" :: "n"(N) : "memory");
}

__device__ __forceinline__ void ldsm4(uint32_t r[4], uint32_t addr) {
    asm volatile("ldmatrix.sync.aligned.m8n8.x4.shared.b16 {%0,%1,%2,%3}, [%4];\n"
                 : "=r"(r[0]), "=r"(r[1]), "=r"(r[2]), "=r"(r[3]) : "r"(addr));
}

__device__ __forceinline__ void mma16816(float c[4], const uint32_t a[4],
                                         uint32_t b0, uint32_t b1) {
    asm volatile("mma.sync.aligned.m16n8k16.row.col.f32.f16.f16.f32 "
                 "{%0,%1,%2,%3}, {%4,%5,%6,%7}, {%8,%9}, {%0,%1,%2,%3};\n"
                 : "+f"(c[0]), "+f"(c[1]), "+f"(c[2]), "+f"(c[3])
                 : "r"(a[0]), "r"(a[1]), "r"(a[2]), "r"(a[3]), "r"(b0), "r"(b1));
}

__device__ __forceinline__ float rf16(float v) {
    return __half2float(__float2half_rn(v));
}

// ---------------- GEMM ----------------
__global__ void __launch_bounds__(THREADS, 2)
gemm_kernel(const float* __restrict__ scale, const float* __restrict__ bias,
            float* __restrict__ out, int M, int N, int K)
{
    extern __shared__ __align__(1024) char smem[];
    const uint32_t sA = (uint32_t)__cvta_generic_to_shared(smem);
    const uint32_t sB = sA + STAGES * ASTAGE;

    const int tid  = threadIdx.x;
    const int lane = tid & 31;
    const int warp = tid >> 5;
    const int wm = warp & 3;   // 4 warp rows x 32 M
    const int wn = warp >> 2;  // 2 warp cols x 64 N

    const int m0 = blockIdx.y * BM;
    const int n0 = blockIdx.x * BN;   // x = N: a wave shares the A slab, streams W
    const int KT = K / BK;

    // staging: 1024 x 16B chunks per operand stage, 4 per thread
    uint32_t a_st[4]; const __half* a_g[4]; const __half* b_g[4];
#pragma unroll
    for (int i = 0; i < 4; i++) {
        int chunk = tid + i * THREADS;
        int row = chunk >> 3, c = chunk & 7;
        a_st[i] = swz((uint32_t)(row * 128 + c * 16));
        a_g[i]  = g_X16 + (size_t)(m0 + row) * K + c * 8;
        b_g[i]  = g_W16 + (size_t)(n0 + row) * K + c * 8;
    }

    // ldmatrix base offsets (swizzle xor is row-only -> constant per thread)
    const uint32_t a_off0 = (uint32_t)((wm * 32 + (lane & 15)) * 128 + (lane >> 4) * 16);
    const uint32_t axor   = (a_off0 >> 3) & 0x70;
    const uint32_t b_off0 = (uint32_t)((wn * 64 + ((lane >> 4) & 1) * 8 + (lane & 7)) * 128
                                       + ((lane >> 3) & 1) * 16);
    const uint32_t bxor   = (b_off0 >> 3) & 0x70;

    float acc[2][8][4];
#pragma unroll
    for (int mi = 0; mi < 2; mi++)
#pragma unroll
        for (int ni = 0; ni < 8; ni++)
#pragma unroll
            for (int e = 0; e < 4; e++) acc[mi][ni][e] = 0.f;

    // prologue: stages 0 and 1
#pragma unroll
    for (int s = 0; s < 2; s++) {
        const size_t ko = (size_t)s * BK;
#pragma unroll
        for (int i = 0; i < 4; i++) cp_async16(sA + s * ASTAGE + a_st[i], a_g[i] + ko);
#pragma unroll
        for (int i = 0; i < 4; i++) cp_async16(sB + s * BSTAGE + a_st[i], b_g[i] + ko);
        cp_commit();
    }
    cp_wait<1>();          // stage 0 resident
    __syncthreads();

    for (int kt = 0; kt < KT; ++kt) {
        // issue loads for kt+2 into the buffer freed at the end of kt-1
        if (kt + 2 < KT) {
            const int s = (kt + 2) % STAGES;
            const size_t ko = (size_t)(kt + 2) * BK;
#pragma unroll
            for (int i = 0; i < 4; i++) cp_async16(sA + s * ASTAGE + a_st[i], a_g[i] + ko);
#pragma unroll
            for (int i = 0; i < 4; i++) cp_async16(sB + s * BSTAGE + a_st[i], b_g[i] + ko);
            cp_commit();
        }

        // compute stage kt
        const uint32_t Abase = sA + (kt % STAGES) * ASTAGE;
        const uint32_t Bbase = sB + (kt % STAGES) * BSTAGE;
#pragma unroll
        for (int ks = 0; ks < 4; ++ks) {
            uint32_t a[2][4];
#pragma unroll
            for (int mi = 0; mi < 2; mi++)
                ldsm4(a[mi], Abase + ((a_off0 + mi * 2048 + ks * 32) ^ axor));
#pragma unroll
            for (int np = 0; np < 4; np++) {
                uint32_t b[4];
                ldsm4(b, Bbase + ((b_off0 + np * 2048 + ks * 32) ^ bxor));
#pragma unroll
                for (int mi = 0; mi < 2; mi++) {
                    mma16816(acc[mi][2 * np],     a[mi], b[0], b[1]);
                    mma16816(acc[mi][2 * np + 1], a[mi], b[2], b[3]);
                }
            }
        }

        // ensure stage kt+1 resident before next iteration
        if (kt + 1 < KT) {
            if (kt + 2 < KT) cp_wait<1>(); else cp_wait<0>();
            __syncthreads();
        }
    }

    // epilogue: scale + bias, round through fp16, f32 out
    const int gi = lane >> 2;
    const int tl = lane & 3;
#pragma unroll
    for (int ni = 0; ni < 8; ni++) {
        const int n = n0 + wn * 64 + ni * 8 + tl * 2;
        const float s0 = __ldg(scale + n), s1 = __ldg(scale + n + 1);
        const float z0 = __ldg(bias + n),  z1 = __ldg(bias + n + 1);
#pragma unroll
        for (int mi = 0; mi < 2; mi++) {
            const size_t r0 = (size_t)(m0 + wm * 32 + mi * 16 + gi);
            *(float2*)(out + r0 * N + n) =
                make_float2(rf16(acc[mi][ni][0] * s0 + z0), rf16(acc[mi][ni][1] * s1 + z1));
            *(float2*)(out + (r0 + 8) * N + n) =
                make_float2(rf16(acc[mi][ni][2] * s0 + z0), rf16(acc[mi][ni][3] * s1 + z1));
        }
    }
}

struct ForceLoad {
    ForceLoad() {
        cudaFuncAttributes a;
        cudaFuncGetAttributes(&a, (const void*)cvt_x);
        cudaFuncGetAttributes(&a, (const void*)cvt_w);
        cudaFuncGetAttributes(&a, (const void*)gemm_kernel);
        cudaFuncSetAttribute((const void*)gemm_kernel,
                             cudaFuncAttributeMaxDynamicSharedMemorySize, SMEM_TOTAL);
    }
};
ForceLoad g_forceload;

} // namespace

extern "C" void kernel_launch(void* const* d_in, const int* in_sizes, int n_in,
                              void* d_out, int out_size) {
    const float* X     = (const float*)d_in[0];
    const int*   W     = (const int*)d_in[1];
    const float* scale = (const float*)d_in[2];
    const float* bias  = (const float*)d_in[3];
    float* out = (float*)d_out;

    const int n0 = in_sizes[0];
    const int n1 = in_sizes[1];
    const int N  = in_sizes[2];            // 11008
    const int K  = n1 / N;                 // 4096
    const int M  = n0 / K;                 // 8192

    cvt_x<<<(n0 / 8 + 255) / 256, 256>>>(X, n0 / 8);
    cvt_w<<<(n1 / 8 + 255) / 256, 256>>>(W, n1 / 8);

    cudaFuncSetAttribute((const void*)gemm_kernel,
                         cudaFuncAttributeMaxDynamicSharedMemorySize, SMEM_TOTAL);
    dim3 grid(N / BN, M / BM);             // 86 x 64
    gemm_kernel<<<grid, THREADS, SMEM_TOTAL>>>(scale, bias, out, M, N, K);
}